// round 4
// baseline (speedup 1.0000x reference)
#include <cuda_runtime.h>
#include <cuda_bf16.h>
#include <cstdint>

// ===================== problem constants =====================
#define BATCH 1024
#define EMB 512
#define NCLS 200000
#define NT 128                   // classes per CTA tile
#define NTILES 1563              // ceil(NCLS / NT)
#define CPAD (NTILES * NT)       // 200064 padded classes
#define TILE_BYTES 131072        // 128 rows x 512 k x 2B
#define CHUNK_BYTES 32768        // 128 rows x 128 k x 2B
#define SCALE_S 64.0f
#define COS_M 0.877582561890373f
#define SIN_M 0.479425538604203f

// ===================== device scratch =====================
__device__ __align__(1024) unsigned char g_W[(size_t)NTILES * TILE_BYTES]; // ~204.9 MB bf16 tiled
__device__ __align__(1024) unsigned char g_A[8 * TILE_BYTES];              // 1 MB bf16 tiled
__device__ float g_rowsum[BATCH];
__device__ float g_target[BATCH];
__device__ int   g_labels[BATCH];

#define DEVINL __device__ __forceinline__

// ===================== PTX helpers =====================
DEVINL uint32_t smem_u32(const void* p) {
    uint32_t a;
    asm("{ .reg .u64 t; cvta.to.shared.u64 t, %1; cvt.u32.u64 %0, t; }" : "=r"(a) : "l"(p));
    return a;
}

#define MBARRIER_INIT(addr, cnt) \
    asm volatile("mbarrier.init.shared.b64 [%0], %1;" :: "r"((uint32_t)(addr)), "r"((uint32_t)(cnt)) : "memory")

#define MBARRIER_EXPECT_TX(addr, bytes) \
    asm volatile("mbarrier.arrive.expect_tx.shared.b64 _, [%0], %1;" :: "r"((uint32_t)(addr)), "r"((uint32_t)(bytes)) : "memory")

#define MBARRIER_ARRIVE(addr) \
    asm volatile("mbarrier.arrive.shared.b64 _, [%0];" :: "r"((uint32_t)(addr)) : "memory")

#define MBARRIER_WAIT_PARITY(addr, parity) do {                                   \
    asm volatile(                                                                 \
        "{\n\t.reg .pred P1;\n\t"                                                 \
        "WAIT_LOOP_%=:\n\t"                                                       \
        "mbarrier.try_wait.parity.acquire.cta.shared::cta.b64 P1, [%0], %1, 0x989680;\n\t" \
        "@P1 bra.uni WAIT_DONE_%=;\n\t"                                           \
        "bra.uni WAIT_LOOP_%=;\n\t"                                               \
        "WAIT_DONE_%=:\n\t}"                                                      \
        :: "r"((uint32_t)(addr)), "r"((uint32_t)(parity)) : "memory");            \
} while (0)

#define MBAR_INVAL(addr) \
    asm volatile("mbarrier.inval.shared.b64 [%0];" :: "r"((uint32_t)(addr)) : "memory")

// 1D bulk async copy global -> shared with mbarrier complete_tx (sm_90 PTX, no 'a' feature)
#define BULK_G2S(dst_smem, src_gmem, bytes, mbar)                                                   \
    asm volatile("cp.async.bulk.shared::cluster.global.mbarrier::complete_tx::bytes [%0], [%1], %2, [%3];" \
        :: "r"((uint32_t)(dst_smem)), "l"(src_gmem), "r"((uint32_t)(bytes)), "r"((uint32_t)(mbar)) : "memory")

DEVINL void ldsm_x4(uint32_t* r, uint32_t addr) {
    asm volatile("ldmatrix.sync.aligned.m8n8.x4.shared.b16 {%0,%1,%2,%3}, [%4];"
                 : "=r"(r[0]), "=r"(r[1]), "=r"(r[2]), "=r"(r[3]) : "r"(addr));
}

DEVINL void mma16816(float* c, const uint32_t* a, uint32_t b0, uint32_t b1) {
    asm volatile(
        "mma.sync.aligned.m16n8k16.row.col.f32.bf16.bf16.f32 "
        "{%0,%1,%2,%3}, {%4,%5,%6,%7}, {%8,%9}, {%0,%1,%2,%3};"
        : "+f"(c[0]), "+f"(c[1]), "+f"(c[2]), "+f"(c[3])
        : "r"(a[0]), "r"(a[1]), "r"(a[2]), "r"(a[3]), "r"(b0), "r"(b1));
}

// address of element (row, k) bf16 inside a tiled region:
// [k/64 superblock: 16KB][row/8 group: 1KB][SW128 atom: 8 rows x 128B]
DEVINL uint32_t sw_addr(uint32_t base, int row, int k) {
    return base + (uint32_t)(((k >> 6) << 14) + ((row >> 3) << 10) + ((row & 7) << 7)
                             + (((k & 63) << 1) ^ ((row & 7) << 4)));
}

// byte offset of element (rr, k) inside a 128x512 tile (same layout, global-scratch side)
DEVINL uint32_t tile_elem_off(int rr, int k) {
    return (uint32_t)(((k >> 6) << 14) + (((rr & 127) >> 3) << 10) + ((rr & 7) << 7)
                      + (((k & 63) << 1) ^ ((rr & 7) << 4)));
}

// ===================== prep kernels =====================
DEVINL float dot4(float4 v) { return v.x * v.x + v.y * v.y + v.z * v.z + v.w * v.w; }
DEVINL uint32_t pk2(float a, float b) {
    __nv_bfloat162 h = __floats2bfloat162_rn(a, b);
    return *reinterpret_cast<uint32_t*>(&h);
}

DEVINL void norm_row(const float* __restrict__ src, unsigned char* __restrict__ dst,
                     int r, int nvalid, int lane) {
    unsigned char* base = dst + (size_t)(r >> 7) * TILE_BYTES;
    int rr = r & 127;
    uint32_t off0 = tile_elem_off(rr, 8 * lane);
    uint32_t off1 = tile_elem_off(rr, 256 + 8 * lane);
    if (r < nvalid) {
        const float4* s = reinterpret_cast<const float4*>(src + (size_t)r * EMB);
        float4 x0 = s[2 * lane], x1 = s[2 * lane + 1];
        float4 x2 = s[64 + 2 * lane], x3 = s[65 + 2 * lane];
        float ss = dot4(x0) + dot4(x1) + dot4(x2) + dot4(x3);
        #pragma unroll
        for (int o = 16; o; o >>= 1) ss += __shfl_xor_sync(0xFFFFFFFFu, ss, o);
        float inv = 1.0f / fmaxf(sqrtf(ss), 1e-12f);
        uint4 a, b;
        a.x = pk2(x0.x * inv, x0.y * inv); a.y = pk2(x0.z * inv, x0.w * inv);
        a.z = pk2(x1.x * inv, x1.y * inv); a.w = pk2(x1.z * inv, x1.w * inv);
        b.x = pk2(x2.x * inv, x2.y * inv); b.y = pk2(x2.z * inv, x2.w * inv);
        b.z = pk2(x3.x * inv, x3.y * inv); b.w = pk2(x3.z * inv, x3.w * inv);
        *reinterpret_cast<uint4*>(base + off0) = a;
        *reinterpret_cast<uint4*>(base + off1) = b;
    } else {
        uint4 z = {0u, 0u, 0u, 0u};
        *reinterpret_cast<uint4*>(base + off0) = z;
        *reinterpret_cast<uint4*>(base + off1) = z;
    }
}

__global__ void k_prep_a(const float* __restrict__ emb) {
    int r = blockIdx.x * 8 + (threadIdx.x >> 5);
    norm_row(emb, g_A, r, BATCH, threadIdx.x & 31);
}

__global__ void k_prep_w(const float* __restrict__ w) {
    int r = blockIdx.x * 8 + (threadIdx.x >> 5);
    norm_row(w, g_W, r, NCLS, threadIdx.x & 31);
}

// labels: detect int64 vs int32 (odd 32-bit words all zero => int64), zero rowsum
__global__ void k_labels(const int* __restrict__ lw) {
    __shared__ int s64;
    int tid = threadIdx.x;
    if (tid == 0) s64 = 1;
    __syncthreads();
    if (tid < 64) {
        if (lw[2 * tid + 1] != 0) atomicExch(&s64, 0);
    }
    __syncthreads();
    int is64 = s64;
    for (int i = tid; i < BATCH; i += 256) {
        g_labels[i] = is64 ? lw[2 * i] : lw[i];
        g_rowsum[i] = 0.0f;
    }
}

// ===================== GEMM + fused arcface/softmax epilogue =====================
// 288 threads: warps 0-7 compute (4 m-groups x 2 n-groups, warp tile 32x64),
// warp 8 lane 0 = async loader. B tile (128x512 bf16 = 128 KB) resident in SMEM.
__global__ __launch_bounds__(288, 1) void k_gemm() {
    extern __shared__ unsigned char smem[];
    uint32_t sb = smem_u32(smem);
    int tid = threadIdx.x, wid = tid >> 5, lane = tid & 31;

    const uint32_t MB_B  = sb + 16;
    const uint32_t MB_AL = sb + 32;   // full barriers [2], 16B apart
    const uint32_t MB_AC = sb + 64;   // consumed barriers [2]
    const uint32_t A_OFF = 1024;
    const uint32_t B_OFF = 66560;     // 1024-aligned; + 128KB => 197632 total

    if (tid == 0) {
        MBARRIER_INIT(MB_B, 1);
        for (int i = 0; i < 2; i++) {
            MBARRIER_INIT(MB_AL + 16 * i, 1);
            MBARRIER_INIT(MB_AC + 16 * i, 8);   // 8 compute warps
        }
    }
    __syncthreads();

    if (wid == 8) {
        if (lane == 0) {
            const unsigned char* srcB = g_W + (size_t)blockIdx.x * TILE_BYTES;
            MBARRIER_EXPECT_TX(MB_B, TILE_BYTES);
            BULK_G2S(sb + B_OFF, srcB, TILE_BYTES, MB_B);
            MBARRIER_EXPECT_TX(MB_AL, CHUNK_BYTES);
            BULK_G2S(sb + A_OFF, g_A, CHUNK_BYTES, MB_AL);
            MBARRIER_EXPECT_TX(MB_AL + 16, CHUNK_BYTES);
            BULK_G2S(sb + A_OFF + CHUNK_BYTES, g_A + CHUNK_BYTES, CHUNK_BYTES, MB_AL + 16);
            int ac_ph[2] = {0, 0};
            for (int g = 2; g < 32; g++) {
                int buf = g & 1;
                MBARRIER_WAIT_PARITY(MB_AC + 16 * buf, ac_ph[buf]); ac_ph[buf] ^= 1;
                MBARRIER_EXPECT_TX(MB_AL + 16 * buf, CHUNK_BYTES);
                BULK_G2S(sb + A_OFF + buf * CHUNK_BYTES, g_A + (size_t)g * CHUNK_BYTES,
                         CHUNK_BYTES, MB_AL + 16 * buf);
            }
        }
    } else {
        int wm = wid & 3, wn = wid >> 2;
        int grp = lane >> 3, r8 = lane & 7;
        // ldmatrix lane coordinates (reg order matches fragment order)
        int a_row = wm * 32 + ((grp & 1) << 3) + r8;   // + i*16
        int a_kof = (grp >> 1) << 3;                   // + ks*16
        int b_n   = wn * 64 + ((grp >> 1) << 3) + r8;  // + jj*16
        int b_kof = (grp & 1) << 3;                    // + k global
        int qr = lane >> 2, ql = lane & 3;
        int cbase = blockIdx.x * NT + wn * 64 + ql * 2;

        MBARRIER_WAIT_PARITY(MB_B, 0);

        int al_ph[2] = {0, 0};
        for (int m = 0; m < 8; m++) {
            float acc[2][8][4];
            #pragma unroll
            for (int i = 0; i < 2; i++)
                #pragma unroll
                for (int j = 0; j < 8; j++)
                    #pragma unroll
                    for (int e = 0; e < 4; e++) acc[i][j][e] = 0.0f;

            #pragma unroll 1
            for (int kc = 0; kc < 4; kc++) {
                int g = m * 4 + kc, buf = g & 1;
                MBARRIER_WAIT_PARITY(MB_AL + 16 * buf, al_ph[buf]); al_ph[buf] ^= 1;
                uint32_t abuf = sb + A_OFF + buf * CHUNK_BYTES;
                #pragma unroll
                for (int ks = 0; ks < 8; ks++) {
                    int k = ks * 16;
                    uint32_t a[2][4], b[4][4];
                    ldsm_x4(a[0], sw_addr(abuf, a_row,      k + a_kof));
                    ldsm_x4(a[1], sw_addr(abuf, a_row + 16, k + a_kof));
                    #pragma unroll
                    for (int jj = 0; jj < 4; jj++)
                        ldsm_x4(b[jj], sw_addr(sb + B_OFF, b_n + jj * 16, kc * 128 + k + b_kof));
                    #pragma unroll
                    for (int i = 0; i < 2; i++)
                        #pragma unroll
                        for (int j = 0; j < 8; j++)
                            mma16816(acc[i][j], a[i], b[j >> 1][(j & 1) * 2], b[j >> 1][(j & 1) * 2 + 1]);
                }
                __syncwarp();
                if (lane == 0) MBARRIER_ARRIVE(MB_AC + 16 * buf);
            }

            // fused epilogue on this m-tile
            #pragma unroll
            for (int i = 0; i < 2; i++) {
                #pragma unroll
                for (int h = 0; h < 2; h++) {
                    int R = m * 128 + wm * 32 + i * 16 + h * 8 + qr;
                    int lbl = g_labels[R];
                    float s = 0.0f;
                    #pragma unroll
                    for (int j = 0; j < 8; j++) {
                        #pragma unroll
                        for (int e = 0; e < 2; e++) {
                            int c = cbase + j * 8 + e;
                            float v = acc[i][j][h * 2 + e];
                            v = fminf(fmaxf(v, -1.0f), 1.0f);
                            float lg;
                            if (c == lbl) {
                                float t = fminf(fmaxf(v, -1.0f + 1e-7f), 1.0f - 1e-7f);
                                float s2 = sqrtf(fmaxf(1.0f - t * t, 0.0f));
                                lg = (t * COS_M - s2 * SIN_M) * SCALE_S;
                                g_target[R] = lg;
                            } else {
                                lg = v * SCALE_S;
                            }
                            if (c < NCLS) s += __expf(lg - 64.0f);
                        }
                    }
                    s += __shfl_xor_sync(0xFFFFFFFFu, s, 1);
                    s += __shfl_xor_sync(0xFFFFFFFFu, s, 2);
                    if (ql == 0) atomicAdd(&g_rowsum[R], s);
                }
            }
        }
    }

    __syncthreads();
    if (tid == 0) {
        MBAR_INVAL(MB_B);
        for (int i = 0; i < 2; i++) { MBAR_INVAL(MB_AL + 16 * i); MBAR_INVAL(MB_AC + 16 * i); }
    }
}

// ===================== final reduction =====================
__global__ void k_final(float* __restrict__ out) {
    __shared__ float sd[BATCH];
    int t = threadIdx.x;
    sd[t] = 64.0f + logf(g_rowsum[t]) - g_target[t];
    __syncthreads();
    for (int s = 512; s > 0; s >>= 1) {
        if (t < s) sd[t] += sd[t + s];
        __syncthreads();
    }
    if (t == 0) out[0] = sd[0] * (1.0f / (float)BATCH);
}

// ===================== launch =====================
extern "C" void kernel_launch(void* const* d_in, const int* in_sizes, int n_in,
                              void* d_out, int out_size) {
    const float* emb = (const float*)d_in[0];
    const float* w   = (const float*)d_in[1];
    const int*   lw  = (const int*)d_in[2];
    float* out = (float*)d_out;

    cudaFuncSetAttribute(k_gemm, cudaFuncAttributeMaxDynamicSharedMemorySize, 197632);

    k_labels<<<1, 256>>>(lw);
    k_prep_a<<<BATCH / 8, 256>>>(emb);
    k_prep_w<<<CPAD / 8, 256>>>(w);
    k_gemm<<<NTILES, 288, 197632>>>();
    k_final<<<1, BATCH>>>(out);
}

// round 5
// speedup vs baseline: 1.1266x; 1.1266x over previous
#include <cuda_runtime.h>
#include <cuda_bf16.h>
#include <cstdint>

// ===================== problem constants =====================
#define BATCH 1024
#define EMB 512
#define NCLS 200000
#define NT 128                   // classes per CTA tile
#define NTILES 1563              // ceil(NCLS / NT)
#define TILE_BYTES 131072        // 128 rows x 512 k x 2B (A m-tile)
#define CHUNK_BYTES 16384        // 128 rows x 64 k x 2B
#define NCHUNKS 64               // 8 m-tiles x 8 k-superblocks
#define NBUF 4
#define SCALE_S 64.0f
#define COS_M 0.877582561890373f
#define SIN_M 0.479425538604203f

// ===================== device scratch =====================
__device__ __align__(1024) unsigned char g_A[8 * TILE_BYTES]; // 1 MB bf16 tiled embeddings
__device__ float g_rowsum[BATCH];
__device__ float g_target[BATCH];
__device__ int   g_labels[BATCH];

#define DEVINL __device__ __forceinline__

// ===================== PTX helpers =====================
DEVINL uint32_t smem_u32(const void* p) {
    uint32_t a;
    asm("{ .reg .u64 t; cvta.to.shared.u64 t, %1; cvt.u32.u64 %0, t; }" : "=r"(a) : "l"(p));
    return a;
}

#define MBARRIER_INIT(addr, cnt) \
    asm volatile("mbarrier.init.shared.b64 [%0], %1;" :: "r"((uint32_t)(addr)), "r"((uint32_t)(cnt)) : "memory")

#define MBARRIER_EXPECT_TX(addr, bytes) \
    asm volatile("mbarrier.arrive.expect_tx.shared.b64 _, [%0], %1;" :: "r"((uint32_t)(addr)), "r"((uint32_t)(bytes)) : "memory")

#define MBARRIER_ARRIVE(addr) \
    asm volatile("mbarrier.arrive.shared.b64 _, [%0];" :: "r"((uint32_t)(addr)) : "memory")

#define MBARRIER_WAIT_PARITY(addr, parity) do {                                   \
    asm volatile(                                                                 \
        "{\n\t.reg .pred P1;\n\t"                                                 \
        "WAIT_LOOP_%=:\n\t"                                                       \
        "mbarrier.try_wait.parity.acquire.cta.shared::cta.b64 P1, [%0], %1, 0x989680;\n\t" \
        "@P1 bra.uni WAIT_DONE_%=;\n\t"                                           \
        "bra.uni WAIT_LOOP_%=;\n\t"                                               \
        "WAIT_DONE_%=:\n\t}"                                                      \
        :: "r"((uint32_t)(addr)), "r"((uint32_t)(parity)) : "memory");            \
} while (0)

#define MBAR_INVAL(addr) \
    asm volatile("mbarrier.inval.shared.b64 [%0];" :: "r"((uint32_t)(addr)) : "memory")

// 1D bulk async copy global -> shared with mbarrier complete_tx (sm_90 baseline PTX)
#define BULK_G2S(dst_smem, src_gmem, bytes, mbar)                                                   \
    asm volatile("cp.async.bulk.shared::cluster.global.mbarrier::complete_tx::bytes [%0], [%1], %2, [%3];" \
        :: "r"((uint32_t)(dst_smem)), "l"(src_gmem), "r"((uint32_t)(bytes)), "r"((uint32_t)(mbar)) : "memory")

DEVINL void ldsm_x4(uint32_t* r, uint32_t addr) {
    asm volatile("ldmatrix.sync.aligned.m8n8.x4.shared.b16 {%0,%1,%2,%3}, [%4];"
                 : "=r"(r[0]), "=r"(r[1]), "=r"(r[2]), "=r"(r[3]) : "r"(addr));
}

DEVINL void mma16816(float* c, const uint32_t* a, uint32_t b0, uint32_t b1) {
    asm volatile(
        "mma.sync.aligned.m16n8k16.row.col.f32.bf16.bf16.f32 "
        "{%0,%1,%2,%3}, {%4,%5,%6,%7}, {%8,%9}, {%0,%1,%2,%3};"
        : "+f"(c[0]), "+f"(c[1]), "+f"(c[2]), "+f"(c[3])
        : "r"(a[0]), "r"(a[1]), "r"(a[2]), "r"(a[3]), "r"(b0), "r"(b1));
}

// address of bf16 element (row, k) inside tiled region:
// [k/64 superblock: 16KB][row/8 group: 1KB][SW128 atom: 8 rows x 128B]
DEVINL uint32_t sw_addr(uint32_t base, int row, int k) {
    return base + (uint32_t)(((k >> 6) << 14) + ((row >> 3) << 10) + ((row & 7) << 7)
                             + (((k & 63) << 1) ^ ((row & 7) << 4)));
}

// byte offset of element (rr, k) inside a 128x512 tile (gmem scratch side, A)
DEVINL uint32_t tile_elem_off(int rr, int k) {
    return (uint32_t)(((k >> 6) << 14) + (((rr & 127) >> 3) << 10) + ((rr & 7) << 7)
                      + (((k & 63) << 1) ^ ((rr & 7) << 4)));
}

// ===================== prep =====================
DEVINL float dot4(float4 v) { return v.x * v.x + v.y * v.y + v.z * v.z + v.w * v.w; }
DEVINL uint32_t pk2(float a, float b) {
    __nv_bfloat162 h = __floats2bfloat162_rn(a, b);
    return *reinterpret_cast<uint32_t*>(&h);
}

__global__ void k_prep_a(const float* __restrict__ emb) {
    int r = blockIdx.x * 8 + (threadIdx.x >> 5);
    int lane = threadIdx.x & 31;
    unsigned char* base = g_A + (size_t)(r >> 7) * TILE_BYTES;
    int rr = r & 127;
    const float4* s = reinterpret_cast<const float4*>(emb + (size_t)r * EMB);
    float4 x0 = s[2 * lane], x1 = s[2 * lane + 1];
    float4 x2 = s[64 + 2 * lane], x3 = s[65 + 2 * lane];
    float ss = dot4(x0) + dot4(x1) + dot4(x2) + dot4(x3);
    #pragma unroll
    for (int o = 16; o; o >>= 1) ss += __shfl_xor_sync(0xFFFFFFFFu, ss, o);
    float inv = 1.0f / fmaxf(sqrtf(ss), 1e-12f);
    uint4 a, b;
    a.x = pk2(x0.x * inv, x0.y * inv); a.y = pk2(x0.z * inv, x0.w * inv);
    a.z = pk2(x1.x * inv, x1.y * inv); a.w = pk2(x1.z * inv, x1.w * inv);
    b.x = pk2(x2.x * inv, x2.y * inv); b.y = pk2(x2.z * inv, x2.w * inv);
    b.z = pk2(x3.x * inv, x3.y * inv); b.w = pk2(x3.z * inv, x3.w * inv);
    *reinterpret_cast<uint4*>(base + tile_elem_off(rr, 8 * lane)) = a;
    *reinterpret_cast<uint4*>(base + tile_elem_off(rr, 256 + 8 * lane)) = b;
}

// labels: detect int64 vs int32 (odd 32-bit words all zero => int64), zero rowsum
__global__ void k_labels(const int* __restrict__ lw) {
    __shared__ int s64;
    int tid = threadIdx.x;
    if (tid == 0) s64 = 1;
    __syncthreads();
    if (tid < 64) {
        if (lw[2 * tid + 1] != 0) atomicExch(&s64, 0);
    }
    __syncthreads();
    int is64 = s64;
    for (int i = tid; i < BATCH; i += 256) {
        g_labels[i] = is64 ? lw[2 * i] : lw[i];
        g_rowsum[i] = 0.0f;
    }
}

// ===================== GEMM + fused W-normalize + arcface/softmax epilogue ===
// 544 threads: warps 0-15 compute (4m x 4n, warp tile 32x32), warp 16 = loader.
// Prologue: compute warps normalize this CTA's 128 raw W rows (f32 LDG) into
// the SMEM-resident bf16 B tile (128x512, SW128 tiled) -> W read from DRAM once.
__global__ __launch_bounds__(544, 1) void k_gemm(const float* __restrict__ wraw) {
    extern __shared__ unsigned char smem[];
    uint32_t sb = smem_u32(smem);
    int tid = threadIdx.x, wid = tid >> 5, lane = tid & 31;

    const uint32_t MB_AL = sb + 32;   // full barriers [4], 16B apart
    const uint32_t MB_AC = sb + 128;  // consumed barriers [4]
    const uint32_t A_OFF = 1024;      // 4 x 16KB chunk buffers
    const uint32_t B_OFF = 66560;     // 1024-aligned; +128KB => 197632 total

    if (tid == 0) {
        for (int i = 0; i < NBUF; i++) {
            MBARRIER_INIT(MB_AL + 16 * i, 1);
            MBARRIER_INIT(MB_AC + 16 * i, 16);   // 16 compute warps
        }
    }
    __syncthreads();

    if (wid == 16) {
        if (lane == 0) {
            // fill all 4 buffers, then stream remaining chunks with backpressure
            #pragma unroll
            for (int g = 0; g < NBUF; g++) {
                MBARRIER_EXPECT_TX(MB_AL + 16 * g, CHUNK_BYTES);
                BULK_G2S(sb + A_OFF + g * CHUNK_BYTES, g_A + (size_t)g * CHUNK_BYTES,
                         CHUNK_BYTES, MB_AL + 16 * g);
            }
            int ac_ph[NBUF] = {0, 0, 0, 0};
            for (int g = NBUF; g < NCHUNKS; g++) {
                int buf = g & (NBUF - 1);
                MBARRIER_WAIT_PARITY(MB_AC + 16 * buf, ac_ph[buf]); ac_ph[buf] ^= 1;
                MBARRIER_EXPECT_TX(MB_AL + 16 * buf, CHUNK_BYTES);
                BULK_G2S(sb + A_OFF + buf * CHUNK_BYTES, g_A + (size_t)g * CHUNK_BYTES,
                         CHUNK_BYTES, MB_AL + 16 * buf);
            }
        }
    } else {
        // ---- prologue: normalize this CTA's W rows into SMEM B tile ----
        #pragma unroll 1
        for (int rr = 0; rr < 8; rr++) {
            int rloc = wid * 8 + rr;
            int c = blockIdx.x * NT + rloc;
            float4 x[4];
            if (c < NCLS) {
                const float4* s = reinterpret_cast<const float4*>(wraw + (size_t)c * EMB);
                #pragma unroll
                for (int q = 0; q < 4; q++) x[q] = s[q * 32 + lane];  // coalesced
            } else {
                #pragma unroll
                for (int q = 0; q < 4; q++) x[q] = make_float4(0.f, 0.f, 0.f, 0.f);
            }
            float ss = dot4(x[0]) + dot4(x[1]) + dot4(x[2]) + dot4(x[3]);
            #pragma unroll
            for (int o = 16; o; o >>= 1) ss += __shfl_xor_sync(0xFFFFFFFFu, ss, o);
            float inv = (c < NCLS) ? (1.0f / fmaxf(sqrtf(ss), 1e-12f)) : 0.0f;
            #pragma unroll
            for (int q = 0; q < 4; q++) {
                uint32_t lo = pk2(x[q].x * inv, x[q].y * inv);
                uint32_t hi = pk2(x[q].z * inv, x[q].w * inv);
                uint32_t addr = sw_addr(sb + B_OFF, rloc, q * 128 + lane * 4);
                asm volatile("st.shared.v2.b32 [%0], {%1, %2};" :: "r"(addr), "r"(lo), "r"(hi) : "memory");
            }
        }
        asm volatile("bar.sync 1, 512;" ::: "memory");   // compute warps only

        // ---- main loop ----
        int wm = wid & 3, wn = wid >> 2;
        int grp = lane >> 3, r8 = lane & 7;
        int a_row = wm * 32 + ((grp & 1) << 3) + r8;   // + i*16
        int a_kof = (grp >> 1) << 3;
        int b_n   = wn * 32 + ((grp >> 1) << 3) + r8;  // + jj*16
        int b_kof = (grp & 1) << 3;
        int qr = lane >> 2, ql = lane & 3;
        int cbase = blockIdx.x * NT + wn * 32 + ql * 2;

        int al_ph[NBUF] = {0, 0, 0, 0};
        #pragma unroll 1
        for (int m = 0; m < 8; m++) {
            float acc[2][4][4];
            #pragma unroll
            for (int i = 0; i < 2; i++)
                #pragma unroll
                for (int j = 0; j < 4; j++)
                    #pragma unroll
                    for (int e = 0; e < 4; e++) acc[i][j][e] = 0.0f;

            #pragma unroll 1
            for (int s = 0; s < 8; s++) {
                int g = m * 8 + s, buf = g & (NBUF - 1);
                MBARRIER_WAIT_PARITY(MB_AL + 16 * buf, al_ph[buf]); al_ph[buf] ^= 1;
                uint32_t abuf = sb + A_OFF + buf * CHUNK_BYTES;
                #pragma unroll
                for (int ks = 0; ks < 4; ks++) {
                    int k = ks * 16;
                    uint32_t a[2][4], b[2][4];
                    ldsm_x4(a[0], sw_addr(abuf, a_row,      k + a_kof));
                    ldsm_x4(a[1], sw_addr(abuf, a_row + 16, k + a_kof));
                    ldsm_x4(b[0], sw_addr(sb + B_OFF, b_n,      s * 64 + k + b_kof));
                    ldsm_x4(b[1], sw_addr(sb + B_OFF, b_n + 16, s * 64 + k + b_kof));
                    if (ks == 3 && lane == 0) MBARRIER_ARRIVE(MB_AC + 16 * buf); // early release
                    #pragma unroll
                    for (int i = 0; i < 2; i++)
                        #pragma unroll
                        for (int j = 0; j < 4; j++)
                            mma16816(acc[i][j], a[i], b[j >> 1][(j & 1) * 2], b[j >> 1][(j & 1) * 2 + 1]);
                }
            }

            // fused epilogue on this m-tile
            #pragma unroll
            for (int i = 0; i < 2; i++) {
                #pragma unroll
                for (int h = 0; h < 2; h++) {
                    int R = m * 128 + wm * 32 + i * 16 + h * 8 + qr;
                    int lbl = g_labels[R];
                    float sum = 0.0f;
                    #pragma unroll
                    for (int j = 0; j < 4; j++) {
                        #pragma unroll
                        for (int e = 0; e < 2; e++) {
                            int c = cbase + j * 8 + e;
                            float v = acc[i][j][h * 2 + e];
                            v = fminf(fmaxf(v, -1.0f), 1.0f);
                            float lg;
                            if (c == lbl) {
                                float t = fminf(fmaxf(v, -1.0f + 1e-7f), 1.0f - 1e-7f);
                                float s2 = sqrtf(fmaxf(1.0f - t * t, 0.0f));
                                lg = (t * COS_M - s2 * SIN_M) * SCALE_S;
                                g_target[R] = lg;
                            } else {
                                lg = v * SCALE_S;
                            }
                            if (c < NCLS) sum += __expf(lg - 64.0f);
                        }
                    }
                    sum += __shfl_xor_sync(0xFFFFFFFFu, sum, 1);
                    sum += __shfl_xor_sync(0xFFFFFFFFu, sum, 2);
                    if (ql == 0) atomicAdd(&g_rowsum[R], sum);
                }
            }
        }
    }

    __syncthreads();
    if (tid == 0) {
        for (int i = 0; i < NBUF; i++) { MBAR_INVAL(MB_AL + 16 * i); MBAR_INVAL(MB_AC + 16 * i); }
    }
}

// ===================== final reduction =====================
__global__ void k_final(float* __restrict__ out) {
    __shared__ float sd[BATCH];
    int t = threadIdx.x;
    sd[t] = 64.0f + logf(g_rowsum[t]) - g_target[t];
    __syncthreads();
    for (int s = 512; s > 0; s >>= 1) {
        if (t < s) sd[t] += sd[t + s];
        __syncthreads();
    }
    if (t == 0) out[0] = sd[0] * (1.0f / (float)BATCH);
}

// ===================== launch =====================
extern "C" void kernel_launch(void* const* d_in, const int* in_sizes, int n_in,
                              void* d_out, int out_size) {
    const float* emb = (const float*)d_in[0];
    const float* w   = (const float*)d_in[1];
    const int*   lw  = (const int*)d_in[2];
    float* out = (float*)d_out;

    cudaFuncSetAttribute(k_gemm, cudaFuncAttributeMaxDynamicSharedMemorySize, 197632);

    k_labels<<<1, 256>>>(lw);
    k_prep_a<<<BATCH / 8, 256>>>(emb);
    k_gemm<<<NTILES, 544, 197632>>>(w);
    k_final<<<1, BATCH>>>(out);
}